// round 2
// baseline (speedup 1.0000x reference)
#include <cuda_runtime.h>
#include <cuda_fp16.h>

#define N_TASK 50000
#define N_RET  20000
#define N_DRAM 5000
#define N_LINKN 100000
#define E_RET  1000000
#define E_DRAM 250000
#define E_LINK 2000000
#define HD 64

// ---------------- device scratch ----------------
__device__ float    g_s_ret[N_RET];
__device__ float    g_s_dram[N_DRAM];
__device__ float    g_s_link[N_LINKN];
__device__ unsigned g_smax[3 * N_TASK];
__device__ unsigned g_smin[3 * N_TASK];
__device__ __half   g_h_task[N_TASK * HD];
__device__ int      g_cnt[N_LINKN];
__device__ int      g_offs[N_LINKN];
__device__ int      g_cursor[N_LINKN];
__device__ int      g_csr[E_LINK];

// order-preserving float<->uint encoding (all real floats encode > 0)
__device__ __forceinline__ unsigned encf(float f) {
    unsigned u = __float_as_uint(f);
    return (u & 0x80000000u) ? ~u : (u | 0x80000000u);
}
__device__ __forceinline__ float decf(unsigned u) {
    return __uint_as_float((u & 0x80000000u) ? (u & 0x7FFFFFFFu) : ~u);
}

// ---------------- init ----------------
__global__ void k_init() {
    int i = blockIdx.x * blockDim.x + threadIdx.x;
    if (i < N_RET)  g_s_ret[i]  = 0.f;
    if (i < N_DRAM) g_s_dram[i] = 0.f;
    if (i < N_LINKN) { g_s_link[i] = 0.f; g_cnt[i] = 0; }
    if (i < N_TASK) {
#pragma unroll
        for (int et = 0; et < 3; et++) {
            g_smax[et * N_TASK + i] = 0u;
            g_smin[et * N_TASK + i] = 0xFFFFFFFFu;
        }
    }
}

// ---------------- pass 1: fused segment sums (+ link histogram) -----------
// 4 edges per thread, vector loads. Ranges: [0,TL) link, [TL,TL+TR) ret, rest dram.
#define TL (E_LINK / 4)
#define TR (E_RET / 4)
#define TD (E_DRAM / 4)

__global__ void k_pass1(const float* __restrict__ fl, const int* __restrict__ ml,
                        const float* __restrict__ fr, const int* __restrict__ mr,
                        const float* __restrict__ fd, const int* __restrict__ md) {
    int i = blockIdx.x * blockDim.x + threadIdx.x;
    if (i < TL) {
        float4 f = ((const float4*)fl)[i];
        int4   m = ((const int4*)ml)[i];
        atomicAdd(&g_s_link[m.x], f.x); atomicAdd(&g_cnt[m.x], 1);
        atomicAdd(&g_s_link[m.y], f.y); atomicAdd(&g_cnt[m.y], 1);
        atomicAdd(&g_s_link[m.z], f.z); atomicAdd(&g_cnt[m.z], 1);
        atomicAdd(&g_s_link[m.w], f.w); atomicAdd(&g_cnt[m.w], 1);
    } else if (i < TL + TR) {
        int j = i - TL;
        float4 f = ((const float4*)fr)[j];
        int4   m = ((const int4*)mr)[j];
        atomicAdd(&g_s_ret[m.x], f.x);
        atomicAdd(&g_s_ret[m.y], f.y);
        atomicAdd(&g_s_ret[m.z], f.z);
        atomicAdd(&g_s_ret[m.w], f.w);
    } else if (i < TL + TR + TD) {
        int j = i - TL - TR;
        float4 f = ((const float4*)fd)[j];
        int4   m = ((const int4*)md)[j];
        atomicAdd(&g_s_dram[m.x], f.x);
        atomicAdd(&g_s_dram[m.y], f.y);
        atomicAdd(&g_s_dram[m.z], f.z);
        atomicAdd(&g_s_dram[m.w], f.w);
    }
}

// ---------------- single-block exclusive scan of g_cnt --------------------
__global__ void k_scan() {
    const int T = 1024, CH = 100;
    __shared__ int sh[T];
    int tid = threadIdx.x;
    int base = tid * CH;
    int s = 0;
    if (base < N_LINKN) {
#pragma unroll
        for (int j = 0; j < CH / 4; j++) {
            int4 c = *(const int4*)&g_cnt[base + j * 4];
            s += c.x + c.y + c.z + c.w;
        }
    }
    sh[tid] = s;
    __syncthreads();
    for (int off = 1; off < T; off <<= 1) {
        int v = (tid >= off) ? sh[tid - off] : 0;
        __syncthreads();
        sh[tid] += v;
        __syncthreads();
    }
    int run = sh[tid] - s;
    if (base < N_LINKN) {
#pragma unroll
        for (int j = 0; j < CH / 4; j++) {
            int4 c = *(const int4*)&g_cnt[base + j * 4];
            int i0 = base + j * 4;
            g_offs[i0 + 0] = run; g_cursor[i0 + 0] = run; run += c.x;
            g_offs[i0 + 1] = run; g_cursor[i0 + 1] = run; run += c.y;
            g_offs[i0 + 2] = run; g_cursor[i0 + 2] = run; run += c.z;
            g_offs[i0 + 3] = run; g_cursor[i0 + 3] = run; run += c.w;
        }
    }
}

// ---------------- pass 2: fused per-task min/max (+ CSR scatter for link) -
__device__ __forceinline__ void mm_edge(const float* s, int m, int t, int et) {
    unsigned k = encf(s[m]);
    atomicMax(&g_smax[et * N_TASK + t], k);
    atomicMin(&g_smin[et * N_TASK + t], k);
}

__global__ void k_pass2(const int* __restrict__ ml, const int* __restrict__ tl,
                        const int* __restrict__ mr, const int* __restrict__ tr,
                        const int* __restrict__ md, const int* __restrict__ td) {
    int i = blockIdx.x * blockDim.x + threadIdx.x;
    if (i < TL) {
        int4 m = ((const int4*)ml)[i];
        int4 t = ((const int4*)tl)[i];
        mm_edge(g_s_link, m.x, t.x, 2);
        mm_edge(g_s_link, m.y, t.y, 2);
        mm_edge(g_s_link, m.z, t.z, 2);
        mm_edge(g_s_link, m.w, t.w, 2);
        int p0 = atomicAdd(&g_cursor[m.x], 1);
        int p1 = atomicAdd(&g_cursor[m.y], 1);
        int p2 = atomicAdd(&g_cursor[m.z], 1);
        int p3 = atomicAdd(&g_cursor[m.w], 1);
        g_csr[p0] = t.x; g_csr[p1] = t.y; g_csr[p2] = t.z; g_csr[p3] = t.w;
    } else if (i < TL + TR) {
        int j = i - TL;
        int4 m = ((const int4*)mr)[j];
        int4 t = ((const int4*)tr)[j];
        mm_edge(g_s_ret, m.x, t.x, 0);
        mm_edge(g_s_ret, m.y, t.y, 0);
        mm_edge(g_s_ret, m.z, t.z, 0);
        mm_edge(g_s_ret, m.w, t.w, 0);
    } else if (i < TL + TR + TD) {
        int j = i - TL - TR;
        int4 m = ((const int4*)md)[j];
        int4 t = ((const int4*)td)[j];
        mm_edge(g_s_dram, m.x, t.x, 1);
        mm_edge(g_s_dram, m.y, t.y, 1);
        mm_edge(g_s_dram, m.z, t.z, 1);
        mm_edge(g_s_dram, m.w, t.w, 1);
    }
}

// ---------------- task update: v[192] -> tanh(v @ Wtask^T + b) ------------
// block = 256 threads, tile = 64 tasks x 64 h, K = 192
__global__ void k_task(const float* __restrict__ Wret,  const float* __restrict__ bret,
                       const float* __restrict__ Wdram, const float* __restrict__ bdram,
                       const float* __restrict__ Wlink, const float* __restrict__ blink,
                       const float* __restrict__ Wtask, const float* __restrict__ btask) {
    extern __shared__ float sh[];
    float* sV  = sh;               // [64][192]
    float* sWt = sh + 64 * 192;    // [192][66] padded

    int tb = blockIdx.x * 64;

    for (int idx = threadIdx.x; idx < 64 * 192; idx += 256) {
        int h = idx / 192, k = idx - h * 192;
        sWt[k * 66 + h] = Wtask[idx];
    }

    for (int idx = threadIdx.x; idx < 64 * 192; idx += 256) {
        int tl = idx / 192, k = idx - tl * 192;
        int et = k >> 6, h = k & 63;
        int t = tb + tl;
        float v = 0.f;
        if (t < N_TASK) {
            unsigned mk = g_smax[et * N_TASK + t];
            if (mk != 0u) {
                const float* We = (et == 0) ? Wret : (et == 1) ? Wdram : Wlink;
                const float* be = (et == 0) ? bret : (et == 1) ? bdram : blink;
                float w = We[h];
                float sv = (w >= 0.f) ? decf(mk) : decf(g_smin[et * N_TASK + t]);
                v = tanhf(fmaf(w, sv, be[h]));
            }
        }
        sV[idx] = v;
    }
    __syncthreads();

    int tx = threadIdx.x & 31, ty = threadIdx.x >> 5;
    int h0 = tx * 2;
    int t0 = ty * 8;
    float acc0[8], acc1[8];
#pragma unroll
    for (int i = 0; i < 8; i++) { acc0[i] = 0.f; acc1[i] = 0.f; }

    const float* vb = sV + t0 * 192;
    for (int k = 0; k < 192; k += 4) {
        float2 w0 = *(const float2*)(sWt + (k + 0) * 66 + h0);
        float2 w1 = *(const float2*)(sWt + (k + 1) * 66 + h0);
        float2 w2 = *(const float2*)(sWt + (k + 2) * 66 + h0);
        float2 w3 = *(const float2*)(sWt + (k + 3) * 66 + h0);
#pragma unroll
        for (int i = 0; i < 8; i++) {
            float4 v = *(const float4*)(vb + i * 192 + k);
            acc0[i] = fmaf(v.x, w0.x, acc0[i]); acc1[i] = fmaf(v.x, w0.y, acc1[i]);
            acc0[i] = fmaf(v.y, w1.x, acc0[i]); acc1[i] = fmaf(v.y, w1.y, acc1[i]);
            acc0[i] = fmaf(v.z, w2.x, acc0[i]); acc1[i] = fmaf(v.z, w2.y, acc1[i]);
            acc0[i] = fmaf(v.w, w3.x, acc0[i]); acc1[i] = fmaf(v.w, w3.y, acc1[i]);
        }
    }

    float b0 = btask[h0], b1 = btask[h0 + 1];
#pragma unroll
    for (int i = 0; i < 8; i++) {
        int t = tb + t0 + i;
        if (t < N_TASK) {
            __half2 o = __floats2half2_rn(tanhf(acc0[i] + b0), tanhf(acc1[i] + b1));
            *(__half2*)&g_h_task[t * 64 + h0] = o;
        }
    }
}

// ---------------- link mean: warp per link node, CSR gather (fp16 h) ------
__global__ void k_linkmean(float* __restrict__ out) {
    int gw = (blockIdx.x * blockDim.x + threadIdx.x) >> 5;
    if (gw >= N_LINKN) return;
    int lane = threadIdx.x & 31;
    int beg = g_offs[gw];
    int n = g_cnt[gw];
    float ax = 0.f, ay = 0.f;
    int j = 0;
    for (; j + 3 < n; j += 4) {
        int t0 = g_csr[beg + j + 0];
        int t1 = g_csr[beg + j + 1];
        int t2 = g_csr[beg + j + 2];
        int t3 = g_csr[beg + j + 3];
        float2 v0 = __half22float2(*(const __half2*)&g_h_task[t0 * 64 + lane * 2]);
        float2 v1 = __half22float2(*(const __half2*)&g_h_task[t1 * 64 + lane * 2]);
        float2 v2 = __half22float2(*(const __half2*)&g_h_task[t2 * 64 + lane * 2]);
        float2 v3 = __half22float2(*(const __half2*)&g_h_task[t3 * 64 + lane * 2]);
        ax += (v0.x + v1.x) + (v2.x + v3.x);
        ay += (v0.y + v1.y) + (v2.y + v3.y);
    }
    for (; j < n; j++) {
        int t = g_csr[beg + j];
        float2 v = __half22float2(*(const __half2*)&g_h_task[t * 64 + lane * 2]);
        ax += v.x;
        ay += v.y;
    }
    float inv = (n > 0) ? 1.0f / (float)n : 0.f;
    float2 o;
    o.x = ax * inv;
    o.y = ay * inv;
    *(float2*)&out[(size_t)gw * 64 + lane * 2] = o;
}

// ---------------- launch ----------------
extern "C" void kernel_launch(void* const* d_in, const int* in_sizes, int n_in,
                              void* d_out, int out_size) {
    const float* feat_ret  = (const float*)d_in[0];
    const float* feat_dram = (const float*)d_in[1];
    const float* feat_link = (const float*)d_in[2];
    const float* W_ret   = (const float*)d_in[3];
    const float* b_ret   = (const float*)d_in[4];
    const float* W_dram  = (const float*)d_in[5];
    const float* b_dram  = (const float*)d_in[6];
    const float* W_link  = (const float*)d_in[7];
    const float* b_link  = (const float*)d_in[8];
    const float* W_task  = (const float*)d_in[9];
    const float* b_task  = (const float*)d_in[10];
    const int* task_ret  = (const int*)d_in[11];
    const int* mod_ret   = (const int*)d_in[12];
    const int* task_dram = (const int*)d_in[13];
    const int* mod_dram  = (const int*)d_in[14];
    const int* task_link = (const int*)d_in[15];
    const int* mod_link  = (const int*)d_in[16];
    float* out = (float*)d_out;

    const int TPB = 256;
    const int NE4 = TL + TR + TD;  // 812500 threads
    const int smem_task = (64 * 192 + 192 * 66) * (int)sizeof(float);  // 99840 B
    cudaFuncSetAttribute(k_task, cudaFuncAttributeMaxDynamicSharedMemorySize, smem_task);

    k_init<<<(N_LINKN + TPB - 1) / TPB, TPB>>>();

    k_pass1<<<(NE4 + TPB - 1) / TPB, TPB>>>(feat_link, mod_link,
                                            feat_ret,  mod_ret,
                                            feat_dram, mod_dram);
    k_scan<<<1, 1024>>>();
    k_pass2<<<(NE4 + TPB - 1) / TPB, TPB>>>(mod_link, task_link,
                                            mod_ret,  task_ret,
                                            mod_dram, task_dram);

    k_task<<<(N_TASK + 63) / 64, TPB, smem_task>>>(W_ret, b_ret, W_dram, b_dram,
                                                   W_link, b_link, W_task, b_task);

    k_linkmean<<<(N_LINKN * 32 + TPB - 1) / TPB, TPB>>>(out);
}

// round 3
// speedup vs baseline: 1.4399x; 1.4399x over previous
#include <cuda_runtime.h>
#include <cuda_fp16.h>

#define N_TASK 50000
#define N_RET  20000
#define N_DRAM 5000
#define N_LINKN 100000
#define E_RET  1000000
#define E_DRAM 250000
#define E_LINK 2000000
#define HD 64

// ---------------- device scratch ----------------
__device__ float    g_s_ret[N_RET];
__device__ float    g_s_dram[N_DRAM];
__device__ float    g_s_link[N_LINKN];
__device__ unsigned g_smax[3 * N_TASK];
__device__ unsigned g_smin[3 * N_TASK];
__device__ __half   g_h_task[N_TASK * HD];
__device__ int      g_cnt[N_LINKN];
__device__ int      g_offs[N_LINKN];
__device__ int      g_cursor[N_LINKN];
__device__ int      g_csr[E_LINK];

// order-preserving float<->uint encoding (all real floats encode > 0)
__device__ __forceinline__ unsigned encf(float f) {
    unsigned u = __float_as_uint(f);
    return (u & 0x80000000u) ? ~u : (u | 0x80000000u);
}
__device__ __forceinline__ float decf(unsigned u) {
    return __uint_as_float((u & 0x80000000u) ? (u & 0x7FFFFFFFu) : ~u);
}

// ---------------- init ----------------
__global__ void k_init() {
    int i = blockIdx.x * blockDim.x + threadIdx.x;
    if (i < N_RET)  g_s_ret[i]  = 0.f;
    if (i < N_DRAM) g_s_dram[i] = 0.f;
    if (i < N_LINKN) { g_s_link[i] = 0.f; g_cnt[i] = 0; }
    if (i < N_TASK) {
#pragma unroll
        for (int et = 0; et < 3; et++) {
            g_smax[et * N_TASK + i] = 0u;
            g_smin[et * N_TASK + i] = 0xFFFFFFFFu;
        }
    }
}

// ---------------- segment sums: 1 edge / thread ----------------
__global__ void k_segsum_link(const float* __restrict__ feat,
                              const int* __restrict__ mod) {
    int e = blockIdx.x * blockDim.x + threadIdx.x;
    if (e >= E_LINK) return;
    int m = __ldg(&mod[e]);
    atomicAdd(&g_s_link[m], __ldg(&feat[e]));
    atomicAdd(&g_cnt[m], 1);
}

__global__ void k_segsum_ret(const float* __restrict__ feat,
                             const int* __restrict__ mod) {
    int e = blockIdx.x * blockDim.x + threadIdx.x;
    if (e >= E_RET) return;
    atomicAdd(&g_s_ret[__ldg(&mod[e])], __ldg(&feat[e]));
}

__global__ void k_segsum_dram(const float* __restrict__ feat,
                              const int* __restrict__ mod) {
    int e = blockIdx.x * blockDim.x + threadIdx.x;
    if (e >= E_DRAM) return;
    atomicAdd(&g_s_dram[__ldg(&mod[e])], __ldg(&feat[e]));
}

// ---------------- single-block exclusive scan of g_cnt --------------------
__global__ void k_scan() {
    const int T = 1024, CH = 100;
    __shared__ int sh[T];
    int tid = threadIdx.x;
    int base = tid * CH;
    int s = 0;
    if (base < N_LINKN) {
#pragma unroll
        for (int j = 0; j < CH / 4; j++) {
            int4 c = *(const int4*)&g_cnt[base + j * 4];
            s += c.x + c.y + c.z + c.w;
        }
    }
    sh[tid] = s;
    __syncthreads();
    for (int off = 1; off < T; off <<= 1) {
        int v = (tid >= off) ? sh[tid - off] : 0;
        __syncthreads();
        sh[tid] += v;
        __syncthreads();
    }
    int run = sh[tid] - s;
    if (base < N_LINKN) {
#pragma unroll
        for (int j = 0; j < CH / 4; j++) {
            int4 c = *(const int4*)&g_cnt[base + j * 4];
            int i0 = base + j * 4;
            g_offs[i0 + 0] = run; g_cursor[i0 + 0] = run; run += c.x;
            g_offs[i0 + 1] = run; g_cursor[i0 + 1] = run; run += c.y;
            g_offs[i0 + 2] = run; g_cursor[i0 + 2] = run; run += c.z;
            g_offs[i0 + 3] = run; g_cursor[i0 + 3] = run; run += c.w;
        }
    }
}

// ---------------- per-task min/max: 1 edge / thread -----------------------
__global__ void k_minmax_link(const int* __restrict__ mod,
                              const int* __restrict__ task) {
    int e = blockIdx.x * blockDim.x + threadIdx.x;
    if (e >= E_LINK) return;
    int m = __ldg(&mod[e]);
    int t = __ldg(&task[e]);
    unsigned k = encf(g_s_link[m]);
    atomicMax(&g_smax[2 * N_TASK + t], k);
    atomicMin(&g_smin[2 * N_TASK + t], k);
    int p = atomicAdd(&g_cursor[m], 1);   // fused CSR scatter
    g_csr[p] = t;
}

__global__ void k_minmax_ret(const int* __restrict__ mod,
                             const int* __restrict__ task) {
    int e = blockIdx.x * blockDim.x + threadIdx.x;
    if (e >= E_RET) return;
    unsigned k = encf(g_s_ret[__ldg(&mod[e])]);
    int t = __ldg(&task[e]);
    atomicMax(&g_smax[0 * N_TASK + t], k);
    atomicMin(&g_smin[0 * N_TASK + t], k);
}

__global__ void k_minmax_dram(const int* __restrict__ mod,
                              const int* __restrict__ task) {
    int e = blockIdx.x * blockDim.x + threadIdx.x;
    if (e >= E_DRAM) return;
    unsigned k = encf(g_s_dram[__ldg(&mod[e])]);
    int t = __ldg(&task[e]);
    atomicMax(&g_smax[1 * N_TASK + t], k);
    atomicMin(&g_smin[1 * N_TASK + t], k);
}

// ---------------- task update: v[192] -> tanh(v @ Wtask^T + b) ------------
// block = 256 threads, tile = 64 tasks x 64 h, K = 192
__global__ void k_task(const float* __restrict__ Wret,  const float* __restrict__ bret,
                       const float* __restrict__ Wdram, const float* __restrict__ bdram,
                       const float* __restrict__ Wlink, const float* __restrict__ blink,
                       const float* __restrict__ Wtask, const float* __restrict__ btask) {
    extern __shared__ float sh[];
    float* sV  = sh;               // [64][192]
    float* sWt = sh + 64 * 192;    // [192][66] padded

    int tb = blockIdx.x * 64;

    for (int idx = threadIdx.x; idx < 64 * 192; idx += 256) {
        int h = idx / 192, k = idx - h * 192;
        sWt[k * 66 + h] = Wtask[idx];
    }

    for (int idx = threadIdx.x; idx < 64 * 192; idx += 256) {
        int tl = idx / 192, k = idx - tl * 192;
        int et = k >> 6, h = k & 63;
        int t = tb + tl;
        float v = 0.f;
        if (t < N_TASK) {
            unsigned mk = g_smax[et * N_TASK + t];
            if (mk != 0u) {
                const float* We = (et == 0) ? Wret : (et == 1) ? Wdram : Wlink;
                const float* be = (et == 0) ? bret : (et == 1) ? bdram : blink;
                float w = We[h];
                float sv = (w >= 0.f) ? decf(mk) : decf(g_smin[et * N_TASK + t]);
                v = tanhf(fmaf(w, sv, be[h]));
            }
        }
        sV[idx] = v;
    }
    __syncthreads();

    int tx = threadIdx.x & 31, ty = threadIdx.x >> 5;
    int h0 = tx * 2;
    int t0 = ty * 8;
    float acc0[8], acc1[8];
#pragma unroll
    for (int i = 0; i < 8; i++) { acc0[i] = 0.f; acc1[i] = 0.f; }

    const float* vb = sV + t0 * 192;
    for (int k = 0; k < 192; k += 4) {
        float2 w0 = *(const float2*)(sWt + (k + 0) * 66 + h0);
        float2 w1 = *(const float2*)(sWt + (k + 1) * 66 + h0);
        float2 w2 = *(const float2*)(sWt + (k + 2) * 66 + h0);
        float2 w3 = *(const float2*)(sWt + (k + 3) * 66 + h0);
#pragma unroll
        for (int i = 0; i < 8; i++) {
            float4 v = *(const float4*)(vb + i * 192 + k);
            acc0[i] = fmaf(v.x, w0.x, acc0[i]); acc1[i] = fmaf(v.x, w0.y, acc1[i]);
            acc0[i] = fmaf(v.y, w1.x, acc0[i]); acc1[i] = fmaf(v.y, w1.y, acc1[i]);
            acc0[i] = fmaf(v.z, w2.x, acc0[i]); acc1[i] = fmaf(v.z, w2.y, acc1[i]);
            acc0[i] = fmaf(v.w, w3.x, acc0[i]); acc1[i] = fmaf(v.w, w3.y, acc1[i]);
        }
    }

    float b0 = btask[h0], b1 = btask[h0 + 1];
#pragma unroll
    for (int i = 0; i < 8; i++) {
        int t = tb + t0 + i;
        if (t < N_TASK) {
            __half2 o = __floats2half2_rn(tanhf(acc0[i] + b0), tanhf(acc1[i] + b1));
            *(__half2*)&g_h_task[t * 64 + h0] = o;
        }
    }
}

// ---------------- link mean: warp per link node, CSR gather (fp16 h) ------
__global__ void k_linkmean(float* __restrict__ out) {
    int gw = (blockIdx.x * blockDim.x + threadIdx.x) >> 5;
    if (gw >= N_LINKN) return;
    int lane = threadIdx.x & 31;
    int beg = g_offs[gw];
    int n = g_cnt[gw];
    float ax = 0.f, ay = 0.f;
    int j = 0;
    for (; j + 3 < n; j += 4) {
        int t0 = __ldg(&g_csr[beg + j + 0]);
        int t1 = __ldg(&g_csr[beg + j + 1]);
        int t2 = __ldg(&g_csr[beg + j + 2]);
        int t3 = __ldg(&g_csr[beg + j + 3]);
        float2 v0 = __half22float2(*(const __half2*)&g_h_task[t0 * 64 + lane * 2]);
        float2 v1 = __half22float2(*(const __half2*)&g_h_task[t1 * 64 + lane * 2]);
        float2 v2 = __half22float2(*(const __half2*)&g_h_task[t2 * 64 + lane * 2]);
        float2 v3 = __half22float2(*(const __half2*)&g_h_task[t3 * 64 + lane * 2]);
        ax += (v0.x + v1.x) + (v2.x + v3.x);
        ay += (v0.y + v1.y) + (v2.y + v3.y);
    }
    for (; j < n; j++) {
        int t = __ldg(&g_csr[beg + j]);
        float2 v = __half22float2(*(const __half2*)&g_h_task[t * 64 + lane * 2]);
        ax += v.x;
        ay += v.y;
    }
    float inv = (n > 0) ? 1.0f / (float)n : 0.f;
    float2 o;
    o.x = ax * inv;
    o.y = ay * inv;
    *(float2*)&out[(size_t)gw * 64 + lane * 2] = o;
}

// ---------------- launch ----------------
extern "C" void kernel_launch(void* const* d_in, const int* in_sizes, int n_in,
                              void* d_out, int out_size) {
    const float* feat_ret  = (const float*)d_in[0];
    const float* feat_dram = (const float*)d_in[1];
    const float* feat_link = (const float*)d_in[2];
    const float* W_ret   = (const float*)d_in[3];
    const float* b_ret   = (const float*)d_in[4];
    const float* W_dram  = (const float*)d_in[5];
    const float* b_dram  = (const float*)d_in[6];
    const float* W_link  = (const float*)d_in[7];
    const float* b_link  = (const float*)d_in[8];
    const float* W_task  = (const float*)d_in[9];
    const float* b_task  = (const float*)d_in[10];
    const int* task_ret  = (const int*)d_in[11];
    const int* mod_ret   = (const int*)d_in[12];
    const int* task_dram = (const int*)d_in[13];
    const int* mod_dram  = (const int*)d_in[14];
    const int* task_link = (const int*)d_in[15];
    const int* mod_link  = (const int*)d_in[16];
    float* out = (float*)d_out;

    const int TPB = 256;
    const int smem_task = (64 * 192 + 192 * 66) * (int)sizeof(float);  // 99840 B
    cudaFuncSetAttribute(k_task, cudaFuncAttributeMaxDynamicSharedMemorySize, smem_task);

    k_init<<<(N_LINKN + TPB - 1) / TPB, TPB>>>();

    k_segsum_link<<<(E_LINK + TPB - 1) / TPB, TPB>>>(feat_link, mod_link);
    k_segsum_ret <<<(E_RET  + TPB - 1) / TPB, TPB>>>(feat_ret,  mod_ret);
    k_segsum_dram<<<(E_DRAM + TPB - 1) / TPB, TPB>>>(feat_dram, mod_dram);

    k_scan<<<1, 1024>>>();

    k_minmax_link<<<(E_LINK + TPB - 1) / TPB, TPB>>>(mod_link, task_link);
    k_minmax_ret <<<(E_RET  + TPB - 1) / TPB, TPB>>>(mod_ret,  task_ret);
    k_minmax_dram<<<(E_DRAM + TPB - 1) / TPB, TPB>>>(mod_dram, task_dram);

    k_task<<<(N_TASK + 63) / 64, TPB, smem_task>>>(W_ret, b_ret, W_dram, b_dram,
                                                   W_link, b_link, W_task, b_task);

    k_linkmean<<<(N_LINKN * 32 + TPB - 1) / TPB, TPB>>>(out);
}

// round 4
// speedup vs baseline: 1.4895x; 1.0345x over previous
#include <cuda_runtime.h>
#include <cuda_fp16.h>

#define N_TASK 50000
#define N_RET  20000
#define N_DRAM 5000
#define N_LINKN 100000
#define E_RET  1000000
#define E_DRAM 250000
#define E_LINK 2000000
#define HD 64

// ---------------- device scratch ----------------
__device__ float    g_s_ret[N_RET];
__device__ float    g_s_dram[N_DRAM];
__device__ float    g_s_link[N_LINKN];
__device__ unsigned g_smax[3 * N_TASK];
__device__ unsigned g_smin[3 * N_TASK];
__device__ __half   g_h_task[N_TASK * HD];
__device__ int      g_cnt[N_LINKN];
__device__ int      g_offs[N_LINKN];
__device__ int      g_cursor[N_LINKN];
__device__ int      g_csr[E_LINK];

// order-preserving float<->uint encoding (all real floats encode > 0)
__device__ __forceinline__ unsigned encf(float f) {
    unsigned u = __float_as_uint(f);
    return (u & 0x80000000u) ? ~u : (u | 0x80000000u);
}
__device__ __forceinline__ float decf(unsigned u) {
    return __uint_as_float((u & 0x80000000u) ? (u & 0x7FFFFFFFu) : ~u);
}

__device__ __forceinline__ float tanh_fast(float x) {
    float y;
    asm("tanh.approx.f32 %0, %1;" : "=f"(y) : "f"(x));
    return y;
}

// ---------------- init ----------------
__global__ void k_init() {
    int i = blockIdx.x * blockDim.x + threadIdx.x;
    if (i < N_RET)  g_s_ret[i]  = 0.f;
    if (i < N_DRAM) g_s_dram[i] = 0.f;
    if (i < N_LINKN) { g_s_link[i] = 0.f; g_cnt[i] = 0; }
    if (i < N_TASK) {
#pragma unroll
        for (int et = 0; et < 3; et++) {
            g_smax[et * N_TASK + i] = 0u;
            g_smin[et * N_TASK + i] = 0xFFFFFFFFu;
        }
    }
}

// ---------------- fused segment sums: 1 edge / thread ----------------
__global__ void k_sum(const float* __restrict__ fl, const int* __restrict__ ml,
                      const float* __restrict__ fr, const int* __restrict__ mr,
                      const float* __restrict__ fd, const int* __restrict__ md) {
    int i = blockIdx.x * blockDim.x + threadIdx.x;
    if (i < E_LINK) {
        int m = __ldg(&ml[i]);
        atomicAdd(&g_s_link[m], __ldg(&fl[i]));
        atomicAdd(&g_cnt[m], 1);
    } else if (i < E_LINK + E_RET) {
        int j = i - E_LINK;
        atomicAdd(&g_s_ret[__ldg(&mr[j])], __ldg(&fr[j]));
    } else if (i < E_LINK + E_RET + E_DRAM) {
        int j = i - E_LINK - E_RET;
        atomicAdd(&g_s_dram[__ldg(&md[j])], __ldg(&fd[j]));
    }
}

// ---------------- single-block exclusive scan of g_cnt --------------------
__global__ void k_scan() {
    const int T = 1024, CH = 100;
    __shared__ int sh[T];
    int tid = threadIdx.x;
    int base = tid * CH;
    int s = 0;
    if (base < N_LINKN) {
#pragma unroll
        for (int j = 0; j < CH / 4; j++) {
            int4 c = *(const int4*)&g_cnt[base + j * 4];
            s += c.x + c.y + c.z + c.w;
        }
    }
    sh[tid] = s;
    __syncthreads();
    for (int off = 1; off < T; off <<= 1) {
        int v = (tid >= off) ? sh[tid - off] : 0;
        __syncthreads();
        sh[tid] += v;
        __syncthreads();
    }
    int run = sh[tid] - s;
    if (base < N_LINKN) {
#pragma unroll
        for (int j = 0; j < CH / 4; j++) {
            int4 c = *(const int4*)&g_cnt[base + j * 4];
            int i0 = base + j * 4;
            g_offs[i0 + 0] = run; g_cursor[i0 + 0] = run; run += c.x;
            g_offs[i0 + 1] = run; g_cursor[i0 + 1] = run; run += c.y;
            g_offs[i0 + 2] = run; g_cursor[i0 + 2] = run; run += c.z;
            g_offs[i0 + 3] = run; g_cursor[i0 + 3] = run; run += c.w;
        }
    }
}

// ---------------- fused per-task min/max (link branch also scatters CSR) --
__global__ void k_mm(const int* __restrict__ ml, const int* __restrict__ tl,
                     const int* __restrict__ mr, const int* __restrict__ tr,
                     const int* __restrict__ md, const int* __restrict__ td) {
    int i = blockIdx.x * blockDim.x + threadIdx.x;
    if (i < E_LINK) {
        int m = __ldg(&ml[i]);
        int t = __ldg(&tl[i]);
        unsigned k = encf(g_s_link[m]);
        atomicMax(&g_smax[2 * N_TASK + t], k);
        atomicMin(&g_smin[2 * N_TASK + t], k);
        int p = atomicAdd(&g_cursor[m], 1);
        g_csr[p] = t;
    } else if (i < E_LINK + E_RET) {
        int j = i - E_LINK;
        unsigned k = encf(g_s_ret[__ldg(&mr[j])]);
        int t = __ldg(&tr[j]);
        atomicMax(&g_smax[0 * N_TASK + t], k);
        atomicMin(&g_smin[0 * N_TASK + t], k);
    } else if (i < E_LINK + E_RET + E_DRAM) {
        int j = i - E_LINK - E_RET;
        unsigned k = encf(g_s_dram[__ldg(&md[j])]);
        int t = __ldg(&td[j]);
        atomicMax(&g_smax[1 * N_TASK + t], k);
        atomicMin(&g_smin[1 * N_TASK + t], k);
    }
}

// ---------------- task update: tanh(v @ Wtask^T + b), f32x2 FFMA ----------
// block = 256 threads (8 warps), tile = 64 tasks x 64 cols, K = 192.
// Thread (lane tx, warp ty): column h = tx + 32*(ty&1), tasks t0 = 16*(ty>>1).
// Accumulators packed f32x2: (even-k partial, odd-k partial).
__global__ void k_task(const float* __restrict__ Wret,  const float* __restrict__ bret,
                       const float* __restrict__ Wdram, const float* __restrict__ bdram,
                       const float* __restrict__ Wlink, const float* __restrict__ blink,
                       const float* __restrict__ Wtask, const float* __restrict__ btask) {
    extern __shared__ float sh[];
    float*  sV  = sh;                          // [64][192] fp32
    float2* sW2 = (float2*)(sh + 64 * 192);    // [64][97] float2 (padded), sW2[h][kp] = (W[h][2kp], W[h][2kp+1])

    int tb = blockIdx.x * 64;

    // load Wtask as k-pairs: row-major per h, padded stride 97
    for (int idx = threadIdx.x; idx < 64 * 96; idx += 256) {
        int h = idx / 96, kp = idx - h * 96;
        sW2[h * 97 + kp] = *(const float2*)&Wtask[h * 192 + 2 * kp];
    }

    // build v[t][k], k = et*64 + h, via monotone max/min trick
    for (int idx = threadIdx.x; idx < 64 * 192; idx += 256) {
        int tl = idx / 192, k = idx - tl * 192;
        int et = k >> 6, h = k & 63;
        int t = tb + tl;
        float v = 0.f;
        if (t < N_TASK) {
            unsigned mk = g_smax[et * N_TASK + t];
            if (mk != 0u) {
                const float* We = (et == 0) ? Wret : (et == 1) ? Wdram : Wlink;
                const float* be = (et == 0) ? bret : (et == 1) ? bdram : blink;
                float w = We[h];
                float sv = (w >= 0.f) ? decf(mk) : decf(g_smin[et * N_TASK + t]);
                v = tanh_fast(fmaf(w, sv, be[h]));
            }
        }
        sV[idx] = v;
    }
    __syncthreads();

    int tx = threadIdx.x & 31, ty = threadIdx.x >> 5;
    int h  = tx + 32 * (ty & 1);
    int t0 = 16 * (ty >> 1);

    unsigned long long acc[16];
#pragma unroll
    for (int i = 0; i < 16; i++) acc[i] = 0ull;

    const float2* wrow = sW2 + h * 97;
    const float*  vb   = sV + t0 * 192;

#pragma unroll 4
    for (int kp = 0; kp < 96; kp += 2) {
        unsigned long long w0 = *(const unsigned long long*)&wrow[kp];
        unsigned long long w1 = *(const unsigned long long*)&wrow[kp + 1];
#pragma unroll
        for (int i = 0; i < 16; i++) {
            ulonglong2 v = *(const ulonglong2*)(vb + i * 192 + 2 * kp);
            asm("fma.rn.f32x2 %0, %1, %2, %0;" : "+l"(acc[i]) : "l"(v.x), "l"(w0));
            asm("fma.rn.f32x2 %0, %1, %2, %0;" : "+l"(acc[i]) : "l"(v.y), "l"(w1));
        }
    }

    float bh = btask[h];
#pragma unroll
    for (int i = 0; i < 16; i++) {
        int t = tb + t0 + i;
        if (t < N_TASK) {
            float lo, hi;
            asm("mov.b64 {%0, %1}, %2;" : "=f"(lo), "=f"(hi) : "l"(acc[i]));
            g_h_task[t * 64 + h] = __float2half(tanhf(lo + hi + bh));
        }
    }
}

// ---------------- link mean: warp per link node, CSR gather (fp16 h) ------
__global__ void k_linkmean(float* __restrict__ out) {
    int gw = (blockIdx.x * blockDim.x + threadIdx.x) >> 5;
    if (gw >= N_LINKN) return;
    int lane = threadIdx.x & 31;
    int beg = g_offs[gw];
    int n = g_cnt[gw];
    float ax = 0.f, ay = 0.f;
    int j = 0;
    for (; j + 3 < n; j += 4) {
        int t0 = __ldg(&g_csr[beg + j + 0]);
        int t1 = __ldg(&g_csr[beg + j + 1]);
        int t2 = __ldg(&g_csr[beg + j + 2]);
        int t3 = __ldg(&g_csr[beg + j + 3]);
        float2 v0 = __half22float2(*(const __half2*)&g_h_task[t0 * 64 + lane * 2]);
        float2 v1 = __half22float2(*(const __half2*)&g_h_task[t1 * 64 + lane * 2]);
        float2 v2 = __half22float2(*(const __half2*)&g_h_task[t2 * 64 + lane * 2]);
        float2 v3 = __half22float2(*(const __half2*)&g_h_task[t3 * 64 + lane * 2]);
        ax += (v0.x + v1.x) + (v2.x + v3.x);
        ay += (v0.y + v1.y) + (v2.y + v3.y);
    }
    for (; j < n; j++) {
        int t = __ldg(&g_csr[beg + j]);
        float2 v = __half22float2(*(const __half2*)&g_h_task[t * 64 + lane * 2]);
        ax += v.x;
        ay += v.y;
    }
    float inv = (n > 0) ? 1.0f / (float)n : 0.f;
    float2 o;
    o.x = ax * inv;
    o.y = ay * inv;
    *(float2*)&out[(size_t)gw * 64 + lane * 2] = o;
}

// ---------------- launch ----------------
extern "C" void kernel_launch(void* const* d_in, const int* in_sizes, int n_in,
                              void* d_out, int out_size) {
    const float* feat_ret  = (const float*)d_in[0];
    const float* feat_dram = (const float*)d_in[1];
    const float* feat_link = (const float*)d_in[2];
    const float* W_ret   = (const float*)d_in[3];
    const float* b_ret   = (const float*)d_in[4];
    const float* W_dram  = (const float*)d_in[5];
    const float* b_dram  = (const float*)d_in[6];
    const float* W_link  = (const float*)d_in[7];
    const float* b_link  = (const float*)d_in[8];
    const float* W_task  = (const float*)d_in[9];
    const float* b_task  = (const float*)d_in[10];
    const int* task_ret  = (const int*)d_in[11];
    const int* mod_ret   = (const int*)d_in[12];
    const int* task_dram = (const int*)d_in[13];
    const int* mod_dram  = (const int*)d_in[14];
    const int* task_link = (const int*)d_in[15];
    const int* mod_link  = (const int*)d_in[16];
    float* out = (float*)d_out;

    const int TPB = 256;
    const int NE = E_LINK + E_RET + E_DRAM;  // 3,250,000
    const int smem_task = 64 * 192 * 4 + 64 * 97 * 8;  // 49152 + 49664 = 98816 B
    cudaFuncSetAttribute(k_task, cudaFuncAttributeMaxDynamicSharedMemorySize, smem_task);

    k_init<<<(N_LINKN + TPB - 1) / TPB, TPB>>>();

    k_sum<<<(NE + TPB - 1) / TPB, TPB>>>(feat_link, mod_link,
                                         feat_ret,  mod_ret,
                                         feat_dram, mod_dram);
    k_scan<<<1, 1024>>>();

    k_mm<<<(NE + TPB - 1) / TPB, TPB>>>(mod_link, task_link,
                                        mod_ret,  task_ret,
                                        mod_dram, task_dram);

    k_task<<<(N_TASK + 63) / 64, TPB, smem_task>>>(W_ret, b_ret, W_dram, b_dram,
                                                   W_link, b_link, W_task, b_task);

    k_linkmean<<<(N_LINKN * 32 + TPB - 1) / TPB, TPB>>>(out);
}

// round 5
// speedup vs baseline: 2.3472x; 1.5758x over previous
#include <cuda_runtime.h>
#include <cuda_fp16.h>

#define N_TASK 50000
#define N_RET  20000
#define N_DRAM 5000
#define N_LINKN 100000
#define E_RET  1000000
#define E_DRAM 250000
#define E_LINK 2000000
#define HD 64
#define SCAN_NBLK 98   /* ceil(100000/1024) */

// ---------------- device scratch ----------------
__device__ float    g_s_ret[N_RET];
__device__ float    g_s_dram[N_DRAM];
__device__ float    g_s_link[N_LINKN];
__device__ unsigned g_smax[3 * N_TASK];
__device__ unsigned g_smin[3 * N_TASK];
__device__ __half   g_h_task[N_TASK * HD];
__device__ int      g_cnt[N_LINKN];
__device__ int      g_offs[N_LINKN];
__device__ int      g_cursor[N_LINKN];
__device__ int      g_csr[E_LINK];
__device__ int      g_part[128];

// order-preserving float<->uint encoding (all real floats encode > 0)
__device__ __forceinline__ unsigned encf(float f) {
    unsigned u = __float_as_uint(f);
    return (u & 0x80000000u) ? ~u : (u | 0x80000000u);
}
__device__ __forceinline__ float decf(unsigned u) {
    return __uint_as_float((u & 0x80000000u) ? (u & 0x7FFFFFFFu) : ~u);
}

__device__ __forceinline__ float tanh_fast(float x) {
    float y;
    asm("tanh.approx.f32 %0, %1;" : "=f"(y) : "f"(x));
    return y;
}

// ---------------- init ----------------
__global__ void k_init() {
    int i = blockIdx.x * blockDim.x + threadIdx.x;
    if (i < N_RET)  g_s_ret[i]  = 0.f;
    if (i < N_DRAM) g_s_dram[i] = 0.f;
    if (i < N_LINKN) { g_s_link[i] = 0.f; g_cnt[i] = 0; }
    if (i < N_TASK) {
#pragma unroll
        for (int et = 0; et < 3; et++) {
            g_smax[et * N_TASK + i] = 0u;
            g_smin[et * N_TASK + i] = 0xFFFFFFFFu;
        }
    }
}

// ---------------- fused segment sums: 1 edge / thread ----------------
__global__ void k_sum(const float* __restrict__ fl, const int* __restrict__ ml,
                      const float* __restrict__ fr, const int* __restrict__ mr,
                      const float* __restrict__ fd, const int* __restrict__ md) {
    int i = blockIdx.x * blockDim.x + threadIdx.x;
    if (i < E_LINK) {
        int m = __ldg(&ml[i]);
        atomicAdd(&g_s_link[m], __ldg(&fl[i]));
        atomicAdd(&g_cnt[m], 1);
    } else if (i < E_LINK + E_RET) {
        int j = i - E_LINK;
        atomicAdd(&g_s_ret[__ldg(&mr[j])], __ldg(&fr[j]));
    } else if (i < E_LINK + E_RET + E_DRAM) {
        int j = i - E_LINK - E_RET;
        atomicAdd(&g_s_dram[__ldg(&md[j])], __ldg(&fd[j]));
    }
}

// ---------------- coalesced 3-phase scan of g_cnt --------------------------
// phase A: per-block sums (1024 counts per block, int4 coalesced)
__global__ void k_scanA() {
    __shared__ int sh[256];
    int b = blockIdx.x, tid = threadIdx.x;
    int i = b * 1024 + tid * 4;
    int s = 0;
    if (i < N_LINKN) {                       // N_LINKN % 4 == 0
        int4 c = *(const int4*)&g_cnt[i];
        s = c.x + c.y + c.z + c.w;
    }
    sh[tid] = s;
    __syncthreads();
    for (int off = 128; off > 0; off >>= 1) {
        if (tid < off) sh[tid] += sh[tid + off];
        __syncthreads();
    }
    if (tid == 0) g_part[b] = sh[0];
}

// phase B: exclusive scan of the 98 partials
__global__ void k_scanB() {
    __shared__ int sh[128];
    int tid = threadIdx.x;
    int v = (tid < SCAN_NBLK) ? g_part[tid] : 0;
    sh[tid] = v;
    __syncthreads();
    for (int off = 1; off < 128; off <<= 1) {
        int u = (tid >= off) ? sh[tid - off] : 0;
        __syncthreads();
        sh[tid] += u;
        __syncthreads();
    }
    if (tid < SCAN_NBLK) g_part[tid] = sh[tid] - v;  // exclusive
}

// phase C: intra-block scan + offset, write offs/cursor coalesced
__global__ void k_scanC() {
    __shared__ int sh[256];
    int b = blockIdx.x, tid = threadIdx.x;
    int i = b * 1024 + tid * 4;
    int4 c = make_int4(0, 0, 0, 0);
    int s = 0;
    if (i < N_LINKN) {
        c = *(const int4*)&g_cnt[i];
        s = c.x + c.y + c.z + c.w;
    }
    sh[tid] = s;
    __syncthreads();
    for (int off = 1; off < 256; off <<= 1) {
        int u = (tid >= off) ? sh[tid - off] : 0;
        __syncthreads();
        sh[tid] += u;
        __syncthreads();
    }
    int run = g_part[b] + sh[tid] - s;       // exclusive prefix for this int4
    if (i < N_LINKN) {
        int4 o;
        o.x = run;
        o.y = run + c.x;
        o.z = o.y + c.y;
        o.w = o.z + c.z;
        *(int4*)&g_offs[i]   = o;
        *(int4*)&g_cursor[i] = o;
    }
}

// ---------------- fused per-task min/max (link branch also scatters CSR) --
__global__ void k_mm(const int* __restrict__ ml, const int* __restrict__ tl,
                     const int* __restrict__ mr, const int* __restrict__ tr,
                     const int* __restrict__ md, const int* __restrict__ td) {
    int i = blockIdx.x * blockDim.x + threadIdx.x;
    if (i < E_LINK) {
        int m = __ldg(&ml[i]);
        int t = __ldg(&tl[i]);
        unsigned k = encf(g_s_link[m]);
        atomicMax(&g_smax[2 * N_TASK + t], k);
        atomicMin(&g_smin[2 * N_TASK + t], k);
        int p = atomicAdd(&g_cursor[m], 1);
        g_csr[p] = t;
    } else if (i < E_LINK + E_RET) {
        int j = i - E_LINK;
        unsigned k = encf(g_s_ret[__ldg(&mr[j])]);
        int t = __ldg(&tr[j]);
        atomicMax(&g_smax[0 * N_TASK + t], k);
        atomicMin(&g_smin[0 * N_TASK + t], k);
    } else if (i < E_LINK + E_RET + E_DRAM) {
        int j = i - E_LINK - E_RET;
        unsigned k = encf(g_s_dram[__ldg(&md[j])]);
        int t = __ldg(&td[j]);
        atomicMax(&g_smax[1 * N_TASK + t], k);
        atomicMin(&g_smin[1 * N_TASK + t], k);
    }
}

// ---------------- task update: tanh(v @ Wtask^T + b), f32x2 FFMA ----------
__global__ void k_task(const float* __restrict__ Wret,  const float* __restrict__ bret,
                       const float* __restrict__ Wdram, const float* __restrict__ bdram,
                       const float* __restrict__ Wlink, const float* __restrict__ blink,
                       const float* __restrict__ Wtask, const float* __restrict__ btask) {
    extern __shared__ float sh[];
    float*  sV  = sh;                          // [64][192] fp32
    float2* sW2 = (float2*)(sh + 64 * 192);    // [64][97] float2 (padded)

    int tb = blockIdx.x * 64;

    for (int idx = threadIdx.x; idx < 64 * 96; idx += 256) {
        int h = idx / 96, kp = idx - h * 96;
        sW2[h * 97 + kp] = *(const float2*)&Wtask[h * 192 + 2 * kp];
    }

    for (int idx = threadIdx.x; idx < 64 * 192; idx += 256) {
        int tl = idx / 192, k = idx - tl * 192;
        int et = k >> 6, h = k & 63;
        int t = tb + tl;
        float v = 0.f;
        if (t < N_TASK) {
            unsigned mk = g_smax[et * N_TASK + t];
            if (mk != 0u) {
                const float* We = (et == 0) ? Wret : (et == 1) ? Wdram : Wlink;
                const float* be = (et == 0) ? bret : (et == 1) ? bdram : blink;
                float w = We[h];
                float sv = (w >= 0.f) ? decf(mk) : decf(g_smin[et * N_TASK + t]);
                v = tanh_fast(fmaf(w, sv, be[h]));
            }
        }
        sV[idx] = v;
    }
    __syncthreads();

    int tx = threadIdx.x & 31, ty = threadIdx.x >> 5;
    int h  = tx + 32 * (ty & 1);
    int t0 = 16 * (ty >> 1);

    unsigned long long acc[16];
#pragma unroll
    for (int i = 0; i < 16; i++) acc[i] = 0ull;

    const float2* wrow = sW2 + h * 97;
    const float*  vb   = sV + t0 * 192;

#pragma unroll 4
    for (int kp = 0; kp < 96; kp += 2) {
        unsigned long long w0 = *(const unsigned long long*)&wrow[kp];
        unsigned long long w1 = *(const unsigned long long*)&wrow[kp + 1];
#pragma unroll
        for (int i = 0; i < 16; i++) {
            ulonglong2 v = *(const ulonglong2*)(vb + i * 192 + 2 * kp);
            asm("fma.rn.f32x2 %0, %1, %2, %0;" : "+l"(acc[i]) : "l"(v.x), "l"(w0));
            asm("fma.rn.f32x2 %0, %1, %2, %0;" : "+l"(acc[i]) : "l"(v.y), "l"(w1));
        }
    }

    float bh = btask[h];
#pragma unroll
    for (int i = 0; i < 16; i++) {
        int t = tb + t0 + i;
        if (t < N_TASK) {
            float lo, hi;
            asm("mov.b64 {%0, %1}, %2;" : "=f"(lo), "=f"(hi) : "l"(acc[i]));
            g_h_task[t * 64 + h] = __float2half(tanhf(lo + hi + bh));
        }
    }
}

// ---------------- link mean: warp per link node, CSR gather (fp16 h) ------
__global__ void k_linkmean(float* __restrict__ out) {
    int gw = (blockIdx.x * blockDim.x + threadIdx.x) >> 5;
    if (gw >= N_LINKN) return;
    int lane = threadIdx.x & 31;
    int beg = g_offs[gw];
    int n = g_cnt[gw];
    float ax = 0.f, ay = 0.f;
    int j = 0;
    for (; j + 3 < n; j += 4) {
        int t0 = __ldg(&g_csr[beg + j + 0]);
        int t1 = __ldg(&g_csr[beg + j + 1]);
        int t2 = __ldg(&g_csr[beg + j + 2]);
        int t3 = __ldg(&g_csr[beg + j + 3]);
        float2 v0 = __half22float2(*(const __half2*)&g_h_task[t0 * 64 + lane * 2]);
        float2 v1 = __half22float2(*(const __half2*)&g_h_task[t1 * 64 + lane * 2]);
        float2 v2 = __half22float2(*(const __half2*)&g_h_task[t2 * 64 + lane * 2]);
        float2 v3 = __half22float2(*(const __half2*)&g_h_task[t3 * 64 + lane * 2]);
        ax += (v0.x + v1.x) + (v2.x + v3.x);
        ay += (v0.y + v1.y) + (v2.y + v3.y);
    }
    for (; j < n; j++) {
        int t = __ldg(&g_csr[beg + j]);
        float2 v = __half22float2(*(const __half2*)&g_h_task[t * 64 + lane * 2]);
        ax += v.x;
        ay += v.y;
    }
    float inv = (n > 0) ? 1.0f / (float)n : 0.f;
    float2 o;
    o.x = ax * inv;
    o.y = ay * inv;
    *(float2*)&out[(size_t)gw * 64 + lane * 2] = o;
}

// ---------------- launch ----------------
extern "C" void kernel_launch(void* const* d_in, const int* in_sizes, int n_in,
                              void* d_out, int out_size) {
    const float* feat_ret  = (const float*)d_in[0];
    const float* feat_dram = (const float*)d_in[1];
    const float* feat_link = (const float*)d_in[2];
    const float* W_ret   = (const float*)d_in[3];
    const float* b_ret   = (const float*)d_in[4];
    const float* W_dram  = (const float*)d_in[5];
    const float* b_dram  = (const float*)d_in[6];
    const float* W_link  = (const float*)d_in[7];
    const float* b_link  = (const float*)d_in[8];
    const float* W_task  = (const float*)d_in[9];
    const float* b_task  = (const float*)d_in[10];
    const int* task_ret  = (const int*)d_in[11];
    const int* mod_ret   = (const int*)d_in[12];
    const int* task_dram = (const int*)d_in[13];
    const int* mod_dram  = (const int*)d_in[14];
    const int* task_link = (const int*)d_in[15];
    const int* mod_link  = (const int*)d_in[16];
    float* out = (float*)d_out;

    const int TPB = 256;
    const int NE = E_LINK + E_RET + E_DRAM;  // 3,250,000
    const int smem_task = 64 * 192 * 4 + 64 * 97 * 8;  // 98816 B
    cudaFuncSetAttribute(k_task, cudaFuncAttributeMaxDynamicSharedMemorySize, smem_task);

    k_init<<<(N_LINKN + TPB - 1) / TPB, TPB>>>();

    k_sum<<<(NE + TPB - 1) / TPB, TPB>>>(feat_link, mod_link,
                                         feat_ret,  mod_ret,
                                         feat_dram, mod_dram);

    k_scanA<<<SCAN_NBLK, 256>>>();
    k_scanB<<<1, 128>>>();
    k_scanC<<<SCAN_NBLK, 256>>>();

    k_mm<<<(NE + TPB - 1) / TPB, TPB>>>(mod_link, task_link,
                                        mod_ret,  task_ret,
                                        mod_dram, task_dram);

    k_task<<<(N_TASK + 63) / 64, TPB, smem_task>>>(W_ret, b_ret, W_dram, b_dram,
                                                   W_link, b_link, W_task, b_task);

    k_linkmean<<<(N_LINKN * 32 + TPB - 1) / TPB, TPB>>>(out);
}

// round 6
// speedup vs baseline: 2.4433x; 1.0409x over previous
#include <cuda_runtime.h>
#include <cuda_fp16.h>

#define N_TASK 50000
#define N_RET  20000
#define N_DRAM 5000
#define N_LINKN 100000
#define E_RET  1000000
#define E_DRAM 250000
#define E_LINK 2000000
#define HD 64
#define SCAN_NBLK 98   /* ceil(100000/1024) */

// ---------------- device scratch ----------------
__device__ float    g_s_ret[N_RET];
__device__ float    g_s_dram[N_DRAM];
__device__ float2   g_sc_link[N_LINKN];   // (sum, count) packed per link node
__device__ unsigned g_smax[3 * N_TASK];
__device__ unsigned g_smin[3 * N_TASK];
__device__ __half   g_h_task[N_TASK * HD];
__device__ int      g_cnt[N_LINKN];
__device__ int      g_offs[N_LINKN];
__device__ int      g_cursor[N_LINKN];
__device__ int      g_csr[E_LINK];
__device__ int      g_part[128];

// order-preserving float<->uint encoding (all real floats encode > 0)
__device__ __forceinline__ unsigned encf(float f) {
    unsigned u = __float_as_uint(f);
    return (u & 0x80000000u) ? ~u : (u | 0x80000000u);
}
__device__ __forceinline__ float decf(unsigned u) {
    return __uint_as_float((u & 0x80000000u) ? (u & 0x7FFFFFFFu) : ~u);
}

__device__ __forceinline__ float tanh_fast(float x) {
    float y;
    asm("tanh.approx.f32 %0, %1;" : "=f"(y) : "f"(x));
    return y;
}

// ---------------- init ----------------
__global__ void k_init() {
    int i = blockIdx.x * blockDim.x + threadIdx.x;
    if (i < N_RET)  g_s_ret[i]  = 0.f;
    if (i < N_DRAM) g_s_dram[i] = 0.f;
    if (i < N_LINKN) g_sc_link[i] = make_float2(0.f, 0.f);
    if (i < N_TASK) {
#pragma unroll
        for (int et = 0; et < 3; et++) {
            g_smax[et * N_TASK + i] = 0u;
            g_smin[et * N_TASK + i] = 0xFFFFFFFFu;
        }
    }
}

// ---------------- fused segment sums: 1 edge / thread ----------------
__global__ void k_sum(const float* __restrict__ fl, const int* __restrict__ ml,
                      const float* __restrict__ fr, const int* __restrict__ mr,
                      const float* __restrict__ fd, const int* __restrict__ md) {
    int i = blockIdx.x * blockDim.x + threadIdx.x;
    if (i < E_LINK) {
        int m = __ldg(&ml[i]);
        atomicAdd(&g_sc_link[m], make_float2(__ldg(&fl[i]), 1.0f));  // one v2 RED
    } else if (i < E_LINK + E_RET) {
        int j = i - E_LINK;
        atomicAdd(&g_s_ret[__ldg(&mr[j])], __ldg(&fr[j]));
    } else if (i < E_LINK + E_RET + E_DRAM) {
        int j = i - E_LINK - E_RET;
        atomicAdd(&g_s_dram[__ldg(&md[j])], __ldg(&fd[j]));
    }
}

// ---------------- coalesced 2-phase scan of counts -------------------------
// phase A: per-block sums (1024 counts per block, float4 coalesced)
__global__ void k_scanA() {
    __shared__ int sh[256];
    int b = blockIdx.x, tid = threadIdx.x;
    int i = b * 1024 + tid * 4;           // pair-element index, multiple of 4
    int s = 0;
    if (i < N_LINKN) {                    // N_LINKN % 4 == 0 -> i+3 in range
        float4 a = *(const float4*)&g_sc_link[i];       // pairs i, i+1
        float4 d = *(const float4*)&g_sc_link[i + 2];   // pairs i+2, i+3
        s = (int)a.y + (int)a.w + (int)d.y + (int)d.w;
    }
    sh[tid] = s;
    __syncthreads();
    for (int off = 128; off > 0; off >>= 1) {
        if (tid < off) sh[tid] += sh[tid + off];
        __syncthreads();
    }
    if (tid == 0) g_part[b] = sh[0];
}

// phase C: block offset from partials + intra-block scan, coalesced writes
__global__ void k_scanC() {
    __shared__ int sh[256];
    __shared__ int base_s;
    int b = blockIdx.x, tid = threadIdx.x;

    // sum partials of preceding blocks (b <= 97 < 256)
    sh[tid] = (tid < b) ? g_part[tid] : 0;
    __syncthreads();
    for (int off = 128; off > 0; off >>= 1) {
        if (tid < off) sh[tid] += sh[tid + off];
        __syncthreads();
    }
    if (tid == 0) base_s = sh[0];
    __syncthreads();
    int base = base_s;
    __syncthreads();

    int i = b * 1024 + tid * 4;
    int c0 = 0, c1 = 0, c2 = 0, c3 = 0, s = 0;
    if (i < N_LINKN) {
        float4 a = *(const float4*)&g_sc_link[i];
        float4 d = *(const float4*)&g_sc_link[i + 2];
        c0 = (int)a.y; c1 = (int)a.w; c2 = (int)d.y; c3 = (int)d.w;
        s = c0 + c1 + c2 + c3;
    }
    sh[tid] = s;
    __syncthreads();
    for (int off = 1; off < 256; off <<= 1) {
        int u = (tid >= off) ? sh[tid - off] : 0;
        __syncthreads();
        sh[tid] += u;
        __syncthreads();
    }
    int run = base + sh[tid] - s;
    if (i < N_LINKN) {
        int4 o;
        o.x = run;
        o.y = run + c0;
        o.z = o.y + c1;
        o.w = o.z + c2;
        *(int4*)&g_offs[i]   = o;
        *(int4*)&g_cursor[i] = o;
        *(int4*)&g_cnt[i]    = make_int4(c0, c1, c2, c3);
    }
}

// ---------------- fused per-task min/max (link branch also scatters CSR) --
__global__ void k_mm(const int* __restrict__ ml, const int* __restrict__ tl,
                     const int* __restrict__ mr, const int* __restrict__ tr,
                     const int* __restrict__ md, const int* __restrict__ td) {
    int i = blockIdx.x * blockDim.x + threadIdx.x;
    if (i < E_LINK) {
        int m = __ldg(&ml[i]);
        int t = __ldg(&tl[i]);
        unsigned k = encf(((const float*)g_sc_link)[2 * m]);  // 4B load of .x
        atomicMax(&g_smax[2 * N_TASK + t], k);
        atomicMin(&g_smin[2 * N_TASK + t], k);
        int p = atomicAdd(&g_cursor[m], 1);
        g_csr[p] = t;
    } else if (i < E_LINK + E_RET) {
        int j = i - E_LINK;
        unsigned k = encf(g_s_ret[__ldg(&mr[j])]);
        int t = __ldg(&tr[j]);
        atomicMax(&g_smax[0 * N_TASK + t], k);
        atomicMin(&g_smin[0 * N_TASK + t], k);
    } else if (i < E_LINK + E_RET + E_DRAM) {
        int j = i - E_LINK - E_RET;
        unsigned k = encf(g_s_dram[__ldg(&md[j])]);
        int t = __ldg(&td[j]);
        atomicMax(&g_smax[1 * N_TASK + t], k);
        atomicMin(&g_smin[1 * N_TASK + t], k);
    }
}

// ---------------- task update: tanh(v @ Wtask^T + b), f32x2 FFMA ----------
__global__ void k_task(const float* __restrict__ Wret,  const float* __restrict__ bret,
                       const float* __restrict__ Wdram, const float* __restrict__ bdram,
                       const float* __restrict__ Wlink, const float* __restrict__ blink,
                       const float* __restrict__ Wtask, const float* __restrict__ btask) {
    extern __shared__ float sh[];
    float*  sV  = sh;                          // [64][192] fp32
    float2* sW2 = (float2*)(sh + 64 * 192);    // [64][97] float2 (padded)

    int tb = blockIdx.x * 64;

    for (int idx = threadIdx.x; idx < 64 * 96; idx += 256) {
        int h = idx / 96, kp = idx - h * 96;
        sW2[h * 97 + kp] = *(const float2*)&Wtask[h * 192 + 2 * kp];
    }

    for (int idx = threadIdx.x; idx < 64 * 192; idx += 256) {
        int tl = idx / 192, k = idx - tl * 192;
        int et = k >> 6, h = k & 63;
        int t = tb + tl;
        float v = 0.f;
        if (t < N_TASK) {
            unsigned mk = g_smax[et * N_TASK + t];
            if (mk != 0u) {
                const float* We = (et == 0) ? Wret : (et == 1) ? Wdram : Wlink;
                const float* be = (et == 0) ? bret : (et == 1) ? bdram : blink;
                float w = We[h];
                float sv = (w >= 0.f) ? decf(mk) : decf(g_smin[et * N_TASK + t]);
                v = tanh_fast(fmaf(w, sv, be[h]));
            }
        }
        sV[idx] = v;
    }
    __syncthreads();

    int tx = threadIdx.x & 31, ty = threadIdx.x >> 5;
    int h  = tx + 32 * (ty & 1);
    int t0 = 16 * (ty >> 1);

    unsigned long long acc[16];
#pragma unroll
    for (int i = 0; i < 16; i++) acc[i] = 0ull;

    const float2* wrow = sW2 + h * 97;
    const float*  vb   = sV + t0 * 192;

#pragma unroll 4
    for (int kp = 0; kp < 96; kp += 2) {
        unsigned long long w0 = *(const unsigned long long*)&wrow[kp];
        unsigned long long w1 = *(const unsigned long long*)&wrow[kp + 1];
#pragma unroll
        for (int i = 0; i < 16; i++) {
            ulonglong2 v = *(const ulonglong2*)(vb + i * 192 + 2 * kp);
            asm("fma.rn.f32x2 %0, %1, %2, %0;" : "+l"(acc[i]) : "l"(v.x), "l"(w0));
            asm("fma.rn.f32x2 %0, %1, %2, %0;" : "+l"(acc[i]) : "l"(v.y), "l"(w1));
        }
    }

    float bh = btask[h];
#pragma unroll
    for (int i = 0; i < 16; i++) {
        int t = tb + t0 + i;
        if (t < N_TASK) {
            float lo, hi;
            asm("mov.b64 {%0, %1}, %2;" : "=f"(lo), "=f"(hi) : "l"(acc[i]));
            g_h_task[t * 64 + h] = __float2half(tanhf(lo + hi + bh));
        }
    }
}

// ---------------- link mean: warp per link node, CSR gather (fp16 h) ------
__global__ void k_linkmean(float* __restrict__ out) {
    int gw = (blockIdx.x * blockDim.x + threadIdx.x) >> 5;
    if (gw >= N_LINKN) return;
    int lane = threadIdx.x & 31;
    int beg = g_offs[gw];
    int n = g_cnt[gw];
    float ax = 0.f, ay = 0.f;
    int j = 0;
    for (; j + 3 < n; j += 4) {
        int t0 = __ldg(&g_csr[beg + j + 0]);
        int t1 = __ldg(&g_csr[beg + j + 1]);
        int t2 = __ldg(&g_csr[beg + j + 2]);
        int t3 = __ldg(&g_csr[beg + j + 3]);
        float2 v0 = __half22float2(*(const __half2*)&g_h_task[t0 * 64 + lane * 2]);
        float2 v1 = __half22float2(*(const __half2*)&g_h_task[t1 * 64 + lane * 2]);
        float2 v2 = __half22float2(*(const __half2*)&g_h_task[t2 * 64 + lane * 2]);
        float2 v3 = __half22float2(*(const __half2*)&g_h_task[t3 * 64 + lane * 2]);
        ax += (v0.x + v1.x) + (v2.x + v3.x);
        ay += (v0.y + v1.y) + (v2.y + v3.y);
    }
    for (; j < n; j++) {
        int t = __ldg(&g_csr[beg + j]);
        float2 v = __half22float2(*(const __half2*)&g_h_task[t * 64 + lane * 2]);
        ax += v.x;
        ay += v.y;
    }
    float inv = (n > 0) ? 1.0f / (float)n : 0.f;
    float2 o;
    o.x = ax * inv;
    o.y = ay * inv;
    *(float2*)&out[(size_t)gw * 64 + lane * 2] = o;
}

// ---------------- launch ----------------
extern "C" void kernel_launch(void* const* d_in, const int* in_sizes, int n_in,
                              void* d_out, int out_size) {
    const float* feat_ret  = (const float*)d_in[0];
    const float* feat_dram = (const float*)d_in[1];
    const float* feat_link = (const float*)d_in[2];
    const float* W_ret   = (const float*)d_in[3];
    const float* b_ret   = (const float*)d_in[4];
    const float* W_dram  = (const float*)d_in[5];
    const float* b_dram  = (const float*)d_in[6];
    const float* W_link  = (const float*)d_in[7];
    const float* b_link  = (const float*)d_in[8];
    const float* W_task  = (const float*)d_in[9];
    const float* b_task  = (const float*)d_in[10];
    const int* task_ret  = (const int*)d_in[11];
    const int* mod_ret   = (const int*)d_in[12];
    const int* task_dram = (const int*)d_in[13];
    const int* mod_dram  = (const int*)d_in[14];
    const int* task_link = (const int*)d_in[15];
    const int* mod_link  = (const int*)d_in[16];
    float* out = (float*)d_out;

    const int TPB = 256;
    const int NE = E_LINK + E_RET + E_DRAM;  // 3,250,000
    const int smem_task = 64 * 192 * 4 + 64 * 97 * 8;  // 98816 B
    cudaFuncSetAttribute(k_task, cudaFuncAttributeMaxDynamicSharedMemorySize, smem_task);

    k_init<<<(N_LINKN + TPB - 1) / TPB, TPB>>>();

    k_sum<<<(NE + TPB - 1) / TPB, TPB>>>(feat_link, mod_link,
                                         feat_ret,  mod_ret,
                                         feat_dram, mod_dram);

    k_scanA<<<SCAN_NBLK, 256>>>();
    k_scanC<<<SCAN_NBLK, 256>>>();

    k_mm<<<(NE + TPB - 1) / TPB, TPB>>>(mod_link, task_link,
                                        mod_ret,  task_ret,
                                        mod_dram, task_dram);

    k_task<<<(N_TASK + 63) / 64, TPB, smem_task>>>(W_ret, b_ret, W_dram, b_dram,
                                                   W_link, b_link, W_task, b_task);

    k_linkmean<<<(N_LINKN * 32 + TPB - 1) / TPB, TPB>>>(out);
}

// round 7
// speedup vs baseline: 2.6897x; 1.1008x over previous
#include <cuda_runtime.h>
#include <cuda_fp16.h>

#define N_TASK 50000
#define N_RET  20000
#define N_DRAM 5000
#define N_LINKN 100000
#define E_RET  1000000
#define E_DRAM 250000
#define E_LINK 2000000
#define HD 64
#define SCAN_NBLK 98   /* ceil(100000/1024) */

// ---------------- device scratch ----------------
__device__ float    g_s_ret[N_RET];
__device__ float    g_s_dram[N_DRAM];
__device__ float2   g_sc_link[N_LINKN];   // (sum, count) packed per link node
__device__ uint2    g_mm[3 * N_TASK];     // (max_enc, min_enc) per (etype, task)
__device__ __half   g_h_task[N_TASK * HD];
__device__ int      g_cnt[N_LINKN];
__device__ int      g_offs[N_LINKN];
__device__ int      g_rank[E_LINK];       // edge's rank within its module
__device__ int      g_csr[E_LINK];
__device__ int      g_part[128];

// order-preserving float<->uint encoding (all real floats encode > 0)
__device__ __forceinline__ unsigned encf(float f) {
    unsigned u = __float_as_uint(f);
    return (u & 0x80000000u) ? ~u : (u | 0x80000000u);
}
__device__ __forceinline__ float decf(unsigned u) {
    return __uint_as_float((u & 0x80000000u) ? (u & 0x7FFFFFFFu) : ~u);
}

__device__ __forceinline__ float tanh_fast(float x) {
    float y;
    asm("tanh.approx.f32 %0, %1;" : "=f"(y) : "f"(x));
    return y;
}

// ---------------- init ----------------
__global__ void k_init() {
    int i = blockIdx.x * blockDim.x + threadIdx.x;
    if (i < N_RET)  g_s_ret[i]  = 0.f;
    if (i < N_DRAM) g_s_dram[i] = 0.f;
    if (i < N_LINKN) g_sc_link[i] = make_float2(0.f, 0.f);
    if (i < N_TASK) {
#pragma unroll
        for (int et = 0; et < 3; et++)
            g_mm[et * N_TASK + i] = make_uint2(0u, 0xFFFFFFFFu);
    }
}

// ---------------- fused segment sums: 1 edge / thread ----------------
__global__ void k_sum(const float* __restrict__ fl, const int* __restrict__ ml,
                      const float* __restrict__ fr, const int* __restrict__ mr,
                      const float* __restrict__ fd, const int* __restrict__ md) {
    int i = blockIdx.x * blockDim.x + threadIdx.x;
    if (i < E_LINK) {
        int m = __ldg(&ml[i]);
        float2 old = atomicAdd(&g_sc_link[m], make_float2(__ldg(&fl[i]), 1.0f));
        g_rank[i] = (int)old.y;           // this edge's rank within module m
    } else if (i < E_LINK + E_RET) {
        int j = i - E_LINK;
        atomicAdd(&g_s_ret[__ldg(&mr[j])], __ldg(&fr[j]));
    } else if (i < E_LINK + E_RET + E_DRAM) {
        int j = i - E_LINK - E_RET;
        atomicAdd(&g_s_dram[__ldg(&md[j])], __ldg(&fd[j]));
    }
}

// ---------------- coalesced 2-phase scan of counts -------------------------
__global__ void k_scanA() {
    __shared__ int sh[256];
    int b = blockIdx.x, tid = threadIdx.x;
    int i = b * 1024 + tid * 4;
    int s = 0;
    if (i < N_LINKN) {
        float4 a = *(const float4*)&g_sc_link[i];
        float4 d = *(const float4*)&g_sc_link[i + 2];
        s = (int)a.y + (int)a.w + (int)d.y + (int)d.w;
    }
    sh[tid] = s;
    __syncthreads();
    for (int off = 128; off > 0; off >>= 1) {
        if (tid < off) sh[tid] += sh[tid + off];
        __syncthreads();
    }
    if (tid == 0) g_part[b] = sh[0];
}

__global__ void k_scanC() {
    __shared__ int sh[256];
    __shared__ int base_s;
    int b = blockIdx.x, tid = threadIdx.x;

    sh[tid] = (tid < b) ? g_part[tid] : 0;
    __syncthreads();
    for (int off = 128; off > 0; off >>= 1) {
        if (tid < off) sh[tid] += sh[tid + off];
        __syncthreads();
    }
    if (tid == 0) base_s = sh[0];
    __syncthreads();
    int base = base_s;
    __syncthreads();

    int i = b * 1024 + tid * 4;
    int c0 = 0, c1 = 0, c2 = 0, c3 = 0, s = 0;
    if (i < N_LINKN) {
        float4 a = *(const float4*)&g_sc_link[i];
        float4 d = *(const float4*)&g_sc_link[i + 2];
        c0 = (int)a.y; c1 = (int)a.w; c2 = (int)d.y; c3 = (int)d.w;
        s = c0 + c1 + c2 + c3;
    }
    sh[tid] = s;
    __syncthreads();
    for (int off = 1; off < 256; off <<= 1) {
        int u = (tid >= off) ? sh[tid - off] : 0;
        __syncthreads();
        sh[tid] += u;
        __syncthreads();
    }
    int run = base + sh[tid] - s;
    if (i < N_LINKN) {
        int4 o;
        o.x = run;
        o.y = run + c0;
        o.z = o.y + c1;
        o.w = o.z + c2;
        *(int4*)&g_offs[i] = o;
        *(int4*)&g_cnt[i]  = make_int4(c0, c1, c2, c3);
    }
}

// ---------------- fused per-task min/max (link branch also scatters CSR) --
__global__ void k_mm(const int* __restrict__ ml, const int* __restrict__ tl,
                     const int* __restrict__ mr, const int* __restrict__ tr,
                     const int* __restrict__ md, const int* __restrict__ td) {
    int i = blockIdx.x * blockDim.x + threadIdx.x;
    if (i < E_LINK) {
        int m = __ldg(&ml[i]);
        int t = __ldg(&tl[i]);
        unsigned k = encf(((const float*)g_sc_link)[2 * m]);  // 4B load of .x
        atomicMax(&g_mm[2 * N_TASK + t].x, k);
        atomicMin(&g_mm[2 * N_TASK + t].y, k);
        int p = __ldg(&g_offs[m]) + __ldg(&g_rank[i]);        // no cursor atomic
        g_csr[p] = t;
    } else if (i < E_LINK + E_RET) {
        int j = i - E_LINK;
        unsigned k = encf(g_s_ret[__ldg(&mr[j])]);
        int t = __ldg(&tr[j]);
        atomicMax(&g_mm[0 * N_TASK + t].x, k);
        atomicMin(&g_mm[0 * N_TASK + t].y, k);
    } else if (i < E_LINK + E_RET + E_DRAM) {
        int j = i - E_LINK - E_RET;
        unsigned k = encf(g_s_dram[__ldg(&md[j])]);
        int t = __ldg(&td[j]);
        atomicMax(&g_mm[1 * N_TASK + t].x, k);
        atomicMin(&g_mm[1 * N_TASK + t].y, k);
    }
}

// ---------------- task update: tanh(v @ Wtask^T + b), f32x2 FFMA ----------
// smem layout: sV[64][192] | sW2[64][97] float2 | sMM[64][3] uint2 | sWe[3][64] | sBe[3][64]
__global__ void k_task(const float* __restrict__ Wret,  const float* __restrict__ bret,
                       const float* __restrict__ Wdram, const float* __restrict__ bdram,
                       const float* __restrict__ Wlink, const float* __restrict__ blink,
                       const float* __restrict__ Wtask, const float* __restrict__ btask) {
    extern __shared__ float sh[];
    float*  sV  = sh;                                   // 12288 floats
    float2* sW2 = (float2*)(sh + 64 * 192);             // 64*97 float2
    uint2*  sMM = (uint2*)(sh + 64 * 192 + 64 * 97 * 2);// 192 uint2
    float*  sWe = (float*)(sMM + 192);                  // 192 floats
    float*  sBe = sWe + 192;                            // 192 floats

    int tb = blockIdx.x * 64;
    int tid = threadIdx.x;

    // stage per-etype weights/biases and per-task min/max bounds
    if (tid < 192) {
        int et = tid >> 6, hh = tid & 63;
        const float* We = (et == 0) ? Wret : (et == 1) ? Wdram : Wlink;
        const float* be = (et == 0) ? bret : (et == 1) ? bdram : blink;
        sWe[tid] = We[hh];
        sBe[tid] = be[hh];
        // reuse: thread tid also stages sMM entry (tl = tid/3 layout below)
    }
    for (int idx = tid; idx < 64 * 3; idx += 256) {
        int tl = idx / 3, et = idx - tl * 3;
        int t = tb + tl;
        sMM[tl * 3 + et] = (t < N_TASK) ? g_mm[et * N_TASK + t]
                                        : make_uint2(0u, 0xFFFFFFFFu);
    }
    for (int idx = tid; idx < 64 * 96; idx += 256) {
        int h = idx / 96, kp = idx - h * 96;
        sW2[h * 97 + kp] = *(const float2*)&Wtask[h * 192 + 2 * kp];
    }
    __syncthreads();

    // build v[t][k], k = et*64 + h, via monotone max/min trick (smem-only)
    for (int idx = tid; idx < 64 * 192; idx += 256) {
        int tl = idx / 192, k = idx - tl * 192;
        int et = k >> 6, h = k & 63;
        float v = 0.f;
        uint2 mm = sMM[tl * 3 + et];
        if (mm.x != 0u) {
            float w = sWe[et * 64 + h];
            float sv = (w >= 0.f) ? decf(mm.x) : decf(mm.y);
            v = tanh_fast(fmaf(w, sv, sBe[et * 64 + h]));
        }
        sV[idx] = v;
    }
    __syncthreads();

    int tx = tid & 31, ty = tid >> 5;
    int h  = tx + 32 * (ty & 1);
    int t0 = 16 * (ty >> 1);

    unsigned long long acc[16];
#pragma unroll
    for (int i = 0; i < 16; i++) acc[i] = 0ull;

    const float2* wrow = sW2 + h * 97;
    const float*  vb   = sV + t0 * 192;

#pragma unroll 4
    for (int kp = 0; kp < 96; kp += 2) {
        unsigned long long w0 = *(const unsigned long long*)&wrow[kp];
        unsigned long long w1 = *(const unsigned long long*)&wrow[kp + 1];
#pragma unroll
        for (int i = 0; i < 16; i++) {
            ulonglong2 v = *(const ulonglong2*)(vb + i * 192 + 2 * kp);
            asm("fma.rn.f32x2 %0, %1, %2, %0;" : "+l"(acc[i]) : "l"(v.x), "l"(w0));
            asm("fma.rn.f32x2 %0, %1, %2, %0;" : "+l"(acc[i]) : "l"(v.y), "l"(w1));
        }
    }

    float bh = btask[h];
#pragma unroll
    for (int i = 0; i < 16; i++) {
        int t = tb + t0 + i;
        if (t < N_TASK) {
            float lo, hi;
            asm("mov.b64 {%0, %1}, %2;" : "=f"(lo), "=f"(hi) : "l"(acc[i]));
            g_h_task[t * 64 + h] = __float2half(tanhf(lo + hi + bh));
        }
    }
}

// ---------------- link mean: warp per link node, CSR gather (fp16 h) ------
__global__ void k_linkmean(float* __restrict__ out) {
    int gw = (blockIdx.x * blockDim.x + threadIdx.x) >> 5;
    if (gw >= N_LINKN) return;
    int lane = threadIdx.x & 31;
    int beg = g_offs[gw];
    int n = g_cnt[gw];
    float ax = 0.f, ay = 0.f;
    int j = 0;
    for (; j + 3 < n; j += 4) {
        int t0 = __ldg(&g_csr[beg + j + 0]);
        int t1 = __ldg(&g_csr[beg + j + 1]);
        int t2 = __ldg(&g_csr[beg + j + 2]);
        int t3 = __ldg(&g_csr[beg + j + 3]);
        float2 v0 = __half22float2(*(const __half2*)&g_h_task[t0 * 64 + lane * 2]);
        float2 v1 = __half22float2(*(const __half2*)&g_h_task[t1 * 64 + lane * 2]);
        float2 v2 = __half22float2(*(const __half2*)&g_h_task[t2 * 64 + lane * 2]);
        float2 v3 = __half22float2(*(const __half2*)&g_h_task[t3 * 64 + lane * 2]);
        ax += (v0.x + v1.x) + (v2.x + v3.x);
        ay += (v0.y + v1.y) + (v2.y + v3.y);
    }
    for (; j < n; j++) {
        int t = __ldg(&g_csr[beg + j]);
        float2 v = __half22float2(*(const __half2*)&g_h_task[t * 64 + lane * 2]);
        ax += v.x;
        ay += v.y;
    }
    float inv = (n > 0) ? 1.0f / (float)n : 0.f;
    float2 o;
    o.x = ax * inv;
    o.y = ay * inv;
    *(float2*)&out[(size_t)gw * 64 + lane * 2] = o;
}

// ---------------- launch ----------------
extern "C" void kernel_launch(void* const* d_in, const int* in_sizes, int n_in,
                              void* d_out, int out_size) {
    const float* feat_ret  = (const float*)d_in[0];
    const float* feat_dram = (const float*)d_in[1];
    const float* feat_link = (const float*)d_in[2];
    const float* W_ret   = (const float*)d_in[3];
    const float* b_ret   = (const float*)d_in[4];
    const float* W_dram  = (const float*)d_in[5];
    const float* b_dram  = (const float*)d_in[6];
    const float* W_link  = (const float*)d_in[7];
    const float* b_link  = (const float*)d_in[8];
    const float* W_task  = (const float*)d_in[9];
    const float* b_task  = (const float*)d_in[10];
    const int* task_ret  = (const int*)d_in[11];
    const int* mod_ret   = (const int*)d_in[12];
    const int* task_dram = (const int*)d_in[13];
    const int* mod_dram  = (const int*)d_in[14];
    const int* task_link = (const int*)d_in[15];
    const int* mod_link  = (const int*)d_in[16];
    float* out = (float*)d_out;

    const int TPB = 256;
    const int NE = E_LINK + E_RET + E_DRAM;  // 3,250,000
    // sV + sW2 + sMM + sWe + sBe
    const int smem_task = 64 * 192 * 4 + 64 * 97 * 8 + 192 * 8 + 192 * 4 + 192 * 4;
    cudaFuncSetAttribute(k_task, cudaFuncAttributeMaxDynamicSharedMemorySize, smem_task);

    k_init<<<(N_LINKN + TPB - 1) / TPB, TPB>>>();

    k_sum<<<(NE + TPB - 1) / TPB, TPB>>>(feat_link, mod_link,
                                         feat_ret,  mod_ret,
                                         feat_dram, mod_dram);

    k_scanA<<<SCAN_NBLK, 256>>>();
    k_scanC<<<SCAN_NBLK, 256>>>();

    k_mm<<<(NE + TPB - 1) / TPB, TPB>>>(mod_link, task_link,
                                        mod_ret,  task_ret,
                                        mod_dram, task_dram);

    k_task<<<(N_TASK + 63) / 64, TPB, smem_task>>>(W_ret, b_ret, W_dram, b_dram,
                                                   W_link, b_link, W_task, b_task);

    k_linkmean<<<(N_LINKN * 32 + TPB - 1) / TPB, TPB>>>(out);
}

// round 8
// speedup vs baseline: 2.7808x; 1.0339x over previous
#include <cuda_runtime.h>
#include <cuda_fp16.h>

#define N_TASK 50000
#define N_RET  20000
#define N_DRAM 5000
#define N_LINKN 100000
#define E_RET  1000000
#define E_DRAM 250000
#define E_LINK 2000000
#define HD 64
#define SCAN_NBLK 98   /* ceil(100000/1024) */

// ---------------- device scratch ----------------
__device__ float    g_s_ret[N_RET];
__device__ float    g_s_dram[N_DRAM];
__device__ float2   g_sc_link[N_LINKN];   // (sum, count) -> after scan: (sum, offs-bits)
__device__ uint2    g_mm[3 * N_TASK];     // (max_enc, min_enc) per (etype, task)
__device__ __half   g_h_task[N_TASK * HD];
__device__ int      g_cnt[N_LINKN];
__device__ int      g_offs[N_LINKN];
__device__ int      g_rank[E_LINK];       // edge's rank within its module
__device__ int      g_csr[E_LINK];
__device__ int      g_part[128];
__device__ int      g_done;

// order-preserving float<->uint encoding (all real floats encode > 0)
__device__ __forceinline__ unsigned encf(float f) {
    unsigned u = __float_as_uint(f);
    return (u & 0x80000000u) ? ~u : (u | 0x80000000u);
}
__device__ __forceinline__ float decf(unsigned u) {
    return __uint_as_float((u & 0x80000000u) ? (u & 0x7FFFFFFFu) : ~u);
}

__device__ __forceinline__ float tanh_fast(float x) {
    float y;
    asm("tanh.approx.f32 %0, %1;" : "=f"(y) : "f"(x));
    return y;
}

// ---------------- init ----------------
__global__ void k_init() {
    int i = blockIdx.x * blockDim.x + threadIdx.x;
    if (i == 0) g_done = 0;
    if (i < N_RET)  g_s_ret[i]  = 0.f;
    if (i < N_DRAM) g_s_dram[i] = 0.f;
    if (i < N_LINKN) g_sc_link[i] = make_float2(0.f, 0.f);
    if (i < N_TASK) {
#pragma unroll
        for (int et = 0; et < 3; et++)
            g_mm[et * N_TASK + i] = make_uint2(0u, 0xFFFFFFFFu);
    }
}

// ---------------- fused segment sums: 1 edge / thread ----------------
__global__ void k_sum(const float* __restrict__ fl, const int* __restrict__ ml,
                      const float* __restrict__ fr, const int* __restrict__ mr,
                      const float* __restrict__ fd, const int* __restrict__ md) {
    int i = blockIdx.x * blockDim.x + threadIdx.x;
    if (i < E_LINK) {
        int m = __ldg(&ml[i]);
        float2 old = atomicAdd(&g_sc_link[m], make_float2(__ldg(&fl[i]), 1.0f));
        g_rank[i] = (int)old.y;           // this edge's rank within module m
    } else if (i < E_LINK + E_RET) {
        int j = i - E_LINK;
        atomicAdd(&g_s_ret[__ldg(&mr[j])], __ldg(&fr[j]));
    } else if (i < E_LINK + E_RET + E_DRAM) {
        int j = i - E_LINK - E_RET;
        atomicAdd(&g_s_dram[__ldg(&md[j])], __ldg(&fd[j]));
    }
}

// ---------------- single-kernel scan: publish partial, spin-join, resume ---
// grid = 98 blocks < 148 SMs -> all co-resident in wave 1 -> spin is safe.
__global__ void k_scan() {
    __shared__ int sh[256];
    int b = blockIdx.x, tid = threadIdx.x;
    int i = b * 1024 + tid * 4;

    int c0 = 0, c1 = 0, c2 = 0, c3 = 0, s = 0;
    if (i < N_LINKN) {
        float4 a = *(const float4*)&g_sc_link[i];
        float4 d = *(const float4*)&g_sc_link[i + 2];
        c0 = (int)a.y; c1 = (int)a.w; c2 = (int)d.y; c3 = (int)d.w;
        s = c0 + c1 + c2 + c3;
    }

    // intra-block inclusive scan of s
    sh[tid] = s;
    __syncthreads();
    for (int off = 1; off < 256; off <<= 1) {
        int u = (tid >= off) ? sh[tid - off] : 0;
        __syncthreads();
        sh[tid] += u;
        __syncthreads();
    }
    int incl = sh[tid];                // inclusive prefix within block
    int blk_total = sh[255];

    // publish block partial, then join
    if (tid == 0) {
        g_part[b] = blk_total;
        __threadfence();
        atomicAdd(&g_done, 1);
        while (*(volatile int*)&g_done < SCAN_NBLK) { }
    }
    __syncthreads();

    // base = sum of preceding blocks' partials (volatile: bypass L1)
    sh[tid] = (tid < b) ? ((volatile int*)g_part)[tid] : 0;
    __syncthreads();
    for (int off = 128; off > 0; off >>= 1) {
        if (tid < off) sh[tid] += sh[tid + off];
        __syncthreads();
    }
    int base = sh[0];

    int run = base + incl - s;         // exclusive prefix for this int4
    if (i < N_LINKN) {
        int4 o;
        o.x = run;
        o.y = run + c0;
        o.z = o.y + c1;
        o.w = o.z + c2;
        *(int4*)&g_offs[i] = o;
        *(int4*)&g_cnt[i]  = make_int4(c0, c1, c2, c3);
        // pack offs bits into g_sc_link[].y so k_mm gets (s, offs) in one 8B load
        int2* scl = (int2*)g_sc_link;
        scl[i + 0].y = o.x;
        scl[i + 1].y = o.y;
        scl[i + 2].y = o.z;
        scl[i + 3].y = o.w;
    }
}

// ---------------- fused per-task min/max (link branch also scatters CSR) --
__global__ void k_mm(const int* __restrict__ ml, const int* __restrict__ tl,
                     const int* __restrict__ mr, const int* __restrict__ tr,
                     const int* __restrict__ md, const int* __restrict__ td) {
    int i = blockIdx.x * blockDim.x + threadIdx.x;
    if (i < E_LINK) {
        int m = __ldg(&ml[i]);
        int t = __ldg(&tl[i]);
        float2 sc = *(const float2*)&g_sc_link[m];   // one 8B scattered load
        unsigned k = encf(sc.x);
        atomicMax(&g_mm[2 * N_TASK + t].x, k);
        atomicMin(&g_mm[2 * N_TASK + t].y, k);
        int p = __float_as_int(sc.y) + __ldg(&g_rank[i]);
        g_csr[p] = t;
    } else if (i < E_LINK + E_RET) {
        int j = i - E_LINK;
        unsigned k = encf(g_s_ret[__ldg(&mr[j])]);
        int t = __ldg(&tr[j]);
        atomicMax(&g_mm[0 * N_TASK + t].x, k);
        atomicMin(&g_mm[0 * N_TASK + t].y, k);
    } else if (i < E_LINK + E_RET + E_DRAM) {
        int j = i - E_LINK - E_RET;
        unsigned k = encf(g_s_dram[__ldg(&md[j])]);
        int t = __ldg(&td[j]);
        atomicMax(&g_mm[1 * N_TASK + t].x, k);
        atomicMin(&g_mm[1 * N_TASK + t].y, k);
    }
}

// ---------------- task update: tanh(v @ Wtask^T + b), f32x2 FFMA ----------
__global__ void k_task(const float* __restrict__ Wret,  const float* __restrict__ bret,
                       const float* __restrict__ Wdram, const float* __restrict__ bdram,
                       const float* __restrict__ Wlink, const float* __restrict__ blink,
                       const float* __restrict__ Wtask, const float* __restrict__ btask) {
    extern __shared__ float sh[];
    float*  sV  = sh;                                   // 12288 floats
    float2* sW2 = (float2*)(sh + 64 * 192);             // 64*97 float2
    uint2*  sMM = (uint2*)(sh + 64 * 192 + 64 * 97 * 2);// 192 uint2
    float*  sWe = (float*)(sMM + 192);                  // 192 floats
    float*  sBe = sWe + 192;                            // 192 floats

    int tb = blockIdx.x * 64;
    int tid = threadIdx.x;

    if (tid < 192) {
        int et = tid >> 6, hh = tid & 63;
        const float* We = (et == 0) ? Wret : (et == 1) ? Wdram : Wlink;
        const float* be = (et == 0) ? bret : (et == 1) ? bdram : blink;
        sWe[tid] = We[hh];
        sBe[tid] = be[hh];
    }
    for (int idx = tid; idx < 64 * 3; idx += 256) {
        int tl = idx / 3, et = idx - tl * 3;
        int t = tb + tl;
        sMM[tl * 3 + et] = (t < N_TASK) ? g_mm[et * N_TASK + t]
                                        : make_uint2(0u, 0xFFFFFFFFu);
    }
    for (int idx = tid; idx < 64 * 96; idx += 256) {
        int h = idx / 96, kp = idx - h * 96;
        sW2[h * 97 + kp] = *(const float2*)&Wtask[h * 192 + 2 * kp];
    }
    __syncthreads();

    for (int idx = tid; idx < 64 * 192; idx += 256) {
        int tl = idx / 192, k = idx - tl * 192;
        int et = k >> 6, h = k & 63;
        float v = 0.f;
        uint2 mm = sMM[tl * 3 + et];
        if (mm.x != 0u) {
            float w = sWe[et * 64 + h];
            float sv = (w >= 0.f) ? decf(mm.x) : decf(mm.y);
            v = tanh_fast(fmaf(w, sv, sBe[et * 64 + h]));
        }
        sV[idx] = v;
    }
    __syncthreads();

    int tx = tid & 31, ty = tid >> 5;
    int h  = tx + 32 * (ty & 1);
    int t0 = 16 * (ty >> 1);

    unsigned long long acc[16];
#pragma unroll
    for (int i = 0; i < 16; i++) acc[i] = 0ull;

    const float2* wrow = sW2 + h * 97;
    const float*  vb   = sV + t0 * 192;

#pragma unroll 4
    for (int kp = 0; kp < 96; kp += 2) {
        unsigned long long w0 = *(const unsigned long long*)&wrow[kp];
        unsigned long long w1 = *(const unsigned long long*)&wrow[kp + 1];
#pragma unroll
        for (int i = 0; i < 16; i++) {
            ulonglong2 v = *(const ulonglong2*)(vb + i * 192 + 2 * kp);
            asm("fma.rn.f32x2 %0, %1, %2, %0;" : "+l"(acc[i]) : "l"(v.x), "l"(w0));
            asm("fma.rn.f32x2 %0, %1, %2, %0;" : "+l"(acc[i]) : "l"(v.y), "l"(w1));
        }
    }

    float bh = btask[h];
#pragma unroll
    for (int i = 0; i < 16; i++) {
        int t = tb + t0 + i;
        if (t < N_TASK) {
            float lo, hi;
            asm("mov.b64 {%0, %1}, %2;" : "=f"(lo), "=f"(hi) : "l"(acc[i]));
            g_h_task[t * 64 + h] = __float2half(tanh_fast(lo + hi + bh));
        }
    }
}

// ---------------- link mean: warp per link node, CSR gather (fp16 h) ------
__global__ void k_linkmean(float* __restrict__ out) {
    int gw = (blockIdx.x * blockDim.x + threadIdx.x) >> 5;
    if (gw >= N_LINKN) return;
    int lane = threadIdx.x & 31;
    int beg = g_offs[gw];
    int n = g_cnt[gw];
    float ax = 0.f, ay = 0.f;
    int j = 0;
    for (; j + 3 < n; j += 4) {
        int t0 = __ldg(&g_csr[beg + j + 0]);
        int t1 = __ldg(&g_csr[beg + j + 1]);
        int t2 = __ldg(&g_csr[beg + j + 2]);
        int t3 = __ldg(&g_csr[beg + j + 3]);
        float2 v0 = __half22float2(*(const __half2*)&g_h_task[t0 * 64 + lane * 2]);
        float2 v1 = __half22float2(*(const __half2*)&g_h_task[t1 * 64 + lane * 2]);
        float2 v2 = __half22float2(*(const __half2*)&g_h_task[t2 * 64 + lane * 2]);
        float2 v3 = __half22float2(*(const __half2*)&g_h_task[t3 * 64 + lane * 2]);
        ax += (v0.x + v1.x) + (v2.x + v3.x);
        ay += (v0.y + v1.y) + (v2.y + v3.y);
    }
    for (; j < n; j++) {
        int t = __ldg(&g_csr[beg + j]);
        float2 v = __half22float2(*(const __half2*)&g_h_task[t * 64 + lane * 2]);
        ax += v.x;
        ay += v.y;
    }
    float inv = (n > 0) ? 1.0f / (float)n : 0.f;
    float2 o;
    o.x = ax * inv;
    o.y = ay * inv;
    *(float2*)&out[(size_t)gw * 64 + lane * 2] = o;
}

// ---------------- launch ----------------
extern "C" void kernel_launch(void* const* d_in, const int* in_sizes, int n_in,
                              void* d_out, int out_size) {
    const float* feat_ret  = (const float*)d_in[0];
    const float* feat_dram = (const float*)d_in[1];
    const float* feat_link = (const float*)d_in[2];
    const float* W_ret   = (const float*)d_in[3];
    const float* b_ret   = (const float*)d_in[4];
    const float* W_dram  = (const float*)d_in[5];
    const float* b_dram  = (const float*)d_in[6];
    const float* W_link  = (const float*)d_in[7];
    const float* b_link  = (const float*)d_in[8];
    const float* W_task  = (const float*)d_in[9];
    const float* b_task  = (const float*)d_in[10];
    const int* task_ret  = (const int*)d_in[11];
    const int* mod_ret   = (const int*)d_in[12];
    const int* task_dram = (const int*)d_in[13];
    const int* mod_dram  = (const int*)d_in[14];
    const int* task_link = (const int*)d_in[15];
    const int* mod_link  = (const int*)d_in[16];
    float* out = (float*)d_out;

    const int TPB = 256;
    const int NE = E_LINK + E_RET + E_DRAM;  // 3,250,000
    const int smem_task = 64 * 192 * 4 + 64 * 97 * 8 + 192 * 8 + 192 * 4 + 192 * 4;
    cudaFuncSetAttribute(k_task, cudaFuncAttributeMaxDynamicSharedMemorySize, smem_task);

    k_init<<<(N_LINKN + TPB - 1) / TPB, TPB>>>();

    k_sum<<<(NE + TPB - 1) / TPB, TPB>>>(feat_link, mod_link,
                                         feat_ret,  mod_ret,
                                         feat_dram, mod_dram);

    k_scan<<<SCAN_NBLK, 256>>>();

    k_mm<<<(NE + TPB - 1) / TPB, TPB>>>(mod_link, task_link,
                                        mod_ret,  task_ret,
                                        mod_dram, task_dram);

    k_task<<<(N_TASK + 63) / 64, TPB, smem_task>>>(W_ret, b_ret, W_dram, b_dram,
                                                   W_link, b_link, W_task, b_task);

    k_linkmean<<<(N_LINKN * 32 + TPB - 1) / TPB, TPB>>>(out);
}